// round 10
// baseline (speedup 1.0000x reference)
#include <cuda_runtime.h>
#include <cstdint>
#include <cstddef>

typedef unsigned long long ull;

// ---------------------------------------------------------------------------
// Packed f32x2 helpers (SASS FFMA2 path — only reachable via explicit PTX)
// ---------------------------------------------------------------------------
__device__ __forceinline__ ull fma2(ull a, ull b, ull c) {
    ull d; asm("fma.rn.f32x2 %0,%1,%2,%3;" : "=l"(d) : "l"(a), "l"(b), "l"(c)); return d;
}
__device__ __forceinline__ ull mul2(ull a, ull b) {
    ull d; asm("mul.rn.f32x2 %0,%1,%2;" : "=l"(d) : "l"(a), "l"(b)); return d;
}
__device__ __forceinline__ ull add2(ull a, ull b) {
    ull d; asm("add.rn.f32x2 %0,%1,%2;" : "=l"(d) : "l"(a), "l"(b)); return d;
}
__device__ __forceinline__ ull pack2(float lo, float hi) {
    ull d; asm("mov.b64 %0,{%1,%2};" : "=l"(d) : "f"(lo), "f"(hi)); return d;
}
__device__ __forceinline__ ull dup2(float x) {
    ull d; asm("mov.b64 %0,{%1,%1};" : "=l"(d) : "f"(x)); return d;
}
__device__ __forceinline__ void unpack2(ull a, float& lo, float& hi) {
    asm("mov.b64 {%0,%1},%2;" : "=f"(lo), "=f"(hi) : "l"(a));
}
__device__ __forceinline__ ull neg2(ull a) { return a ^ 0x8000000080000000ULL; }

// ---------------------------------------------------------------------------
// Compile-time PGA(3,0,1) tables. Blade order matches the reference:
// idx : (), e0,e1,e2,e3, e01,e02,e03,e12,e13,e23, e012,e013,e023,e123, e0123
// ---------------------------------------------------------------------------
namespace ga {

__host__ __device__ constexpr unsigned bladeMask(int i) {
    constexpr unsigned m[16] = {0u,1u,2u,4u,8u, 3u,5u,9u,6u,10u,12u, 7u,11u,13u,14u, 15u};
    return m[i];
}
__host__ __device__ constexpr int idxOfMask(unsigned m) {
    constexpr int t[16] = {0,1,2,5,3,6,8,11,4,7,9,12,10,13,14,15};
    return t[m];
}
__host__ __device__ constexpr int invCnt(unsigned a, unsigned b) {
    int s = 0;
    for (int i = 0; i < 4; ++i)
        if ((b >> i) & 1u)
            for (int j = i + 1; j < 4; ++j)
                if ((a >> j) & 1u) ++s;
    return s;
}
__host__ __device__ constexpr float gpSign(int j, int k) {
    unsigned a = bladeMask(j), b = bladeMask(k);
    if (a & b & 1u) return 0.0f;                   // e0*e0 = 0
    return (invCnt(a, b) & 1) ? -1.0f : 1.0f;
}
__host__ __device__ constexpr int gpTgt(int j, int k) {
    return idxOfMask(bladeMask(j) ^ bladeMask(k));
}
__host__ __device__ constexpr float dSign(int t) {
    unsigned m = bladeMask(t);
    return (invCnt(m, 15u ^ m) & 1) ? -1.0f : 1.0f;
}
__host__ __device__ constexpr float jnCoef(int b, int c) {
    unsigned mb = bladeMask(b), mc = bladeMask(c);
    if ((mb | mc) != 15u) return 0.0f;
    unsigned ma = mb & mc;
    int ia = idxOfMask(15u ^ ma);
    unsigned cb = 15u ^ mb, cc = 15u ^ mc;
    float so = (invCnt(cb, cc) & 1) ? -1.0f : 1.0f;
    return dSign(ia) * so * dSign(b) * dSign(c);
}
__host__ __device__ constexpr int jnTgt(int b, int c) {
    return idxOfMask(bladeMask(b) & bladeMask(c));
}

template<int...> struct iseq {};
template<int N, int... S> struct mkseq : mkseq<N-1, N-1, S...> {};
template<int... S> struct mkseq<0, S...> { using type = iseq<S...>; };

// Row-local negation: only neg2(L[J]) for the CURRENT row is live (1 temp
// register instead of a 16-entry negated array — the R8 register spike).
template<int J, int K>
__device__ __forceinline__ void gpTerm(ull aj, ull naj, const ull (&R)[16], ull (&h)[16]) {
    constexpr float s = gpSign(J, K);
    if constexpr (s > 0.5f) {
        constexpr int t = gpTgt(J, K);
        h[t] = fma2(aj, R[K], h[t]);
    } else if constexpr (s < -0.5f) {
        constexpr int t = gpTgt(J, K);
        h[t] = fma2(naj, R[K], h[t]);
    }
}
template<int J, int... Ks>
__device__ __forceinline__ void gpRow(const ull (&L)[16], const ull (&R)[16],
                                      ull (&h)[16], iseq<Ks...>) {
    const ull aj  = L[J];
    const ull naj = neg2(aj);
    (gpTerm<J, Ks>(aj, naj, R, h), ...);
}
template<int... Js>
__device__ __forceinline__ void gpAll(const ull (&L)[16], const ull (&R)[16],
                                      ull (&h)[16], iseq<Js...>) {
    (gpRow<Js>(L, R, h, typename mkseq<16>::type{}), ...);
}

template<int J, int K>
__device__ __forceinline__ void jnTerm(ull aj, ull naj, const ull (&R)[16], ull (&h)[16]) {
    constexpr float s = jnCoef(J, K);
    if constexpr (s > 0.5f) {
        constexpr int t = jnTgt(J, K);
        h[t] = fma2(aj, R[K], h[t]);
    } else if constexpr (s < -0.5f) {
        constexpr int t = jnTgt(J, K);
        h[t] = fma2(naj, R[K], h[t]);
    }
}
template<int J, int... Ks>
__device__ __forceinline__ void jnRow(const ull (&L)[16], const ull (&R)[16],
                                      ull (&h)[16], iseq<Ks...>) {
    const ull aj  = L[J];
    const ull naj = neg2(aj);
    (jnTerm<J, Ks>(aj, naj, R, h), ...);
}
template<int... Js>
__device__ __forceinline__ void jnAll(const ull (&L)[16], const ull (&R)[16],
                                      ull (&h)[16], iseq<Js...>) {
    (jnRow<Js>(L, R, h, typename mkseq<16>::type{}), ...);
}

// Equivariant-linear accumulation (packed pair), one input channel.
// grades = [0,1,1,1,1, 2,2,2,2,2,2, 3,3,3,3, 4]
// e0 wedge (+1): 1<-0 (w5); 5,6,7<-2,3,4 (w6); 11,12,13<-8,9,10 (w7); 15<-14 (w8)
__device__ __forceinline__ void linAcc2(ull (&o)[16], const ull (&w)[9], const ull (&x)[16]) {
    o[0]  = fma2(w[0], x[0],  o[0]);
    o[1]  = fma2(w[1], x[1],  o[1]);  o[1]  = fma2(w[5], x[0],  o[1]);
    o[2]  = fma2(w[1], x[2],  o[2]);
    o[3]  = fma2(w[1], x[3],  o[3]);
    o[4]  = fma2(w[1], x[4],  o[4]);
    o[5]  = fma2(w[2], x[5],  o[5]);  o[5]  = fma2(w[6], x[2],  o[5]);
    o[6]  = fma2(w[2], x[6],  o[6]);  o[6]  = fma2(w[6], x[3],  o[6]);
    o[7]  = fma2(w[2], x[7],  o[7]);  o[7]  = fma2(w[6], x[4],  o[7]);
    o[8]  = fma2(w[2], x[8],  o[8]);
    o[9]  = fma2(w[2], x[9],  o[9]);
    o[10] = fma2(w[2], x[10], o[10]);
    o[11] = fma2(w[3], x[11], o[11]); o[11] = fma2(w[7], x[8],  o[11]);
    o[12] = fma2(w[3], x[12], o[12]); o[12] = fma2(w[7], x[9],  o[12]);
    o[13] = fma2(w[3], x[13], o[13]); o[13] = fma2(w[7], x[10], o[13]);
    o[14] = fma2(w[3], x[14], o[14]);
    o[15] = fma2(w[4], x[15], o[15]); o[15] = fma2(w[8], x[14], o[15]);
}

} // namespace ga

// ---------------------------------------------------------------------------
// Global (L1-resident) transposed scalar-head weight tables; filled by
// init_tables each call (deterministic, graph-capturable, no allocation).
// ---------------------------------------------------------------------------
__device__ float g_TSA[2048];   // [64 s][32 lane]  lane<16: left_s, else jl_s
__device__ float g_TSB[2048];   // [64 s][32 lane]  lane<16: right_s, else jr_s
__device__ float g_TS0[2048];   // [64 s][32 o]     w_out_s2mv
__device__ float g_TW1[2048];   // [64 s][32 o]     w_out_s2s rows 0..31
__device__ float g_TW2[2048];   // [64 s][32 o]     w_out_s2s rows 32..63
__device__ float g_TM1[1024];   // [32 c][32 o]     w_out_mvs2s rows 0..31
__device__ float g_TM2[1024];   // [32 c][32 o]     w_out_mvs2s rows 32..63

__global__ void init_tables(const float* __restrict__ wLs, const float* __restrict__ wRs,
                            const float* __restrict__ wJLs, const float* __restrict__ wJRs,
                            const float* __restrict__ wS2mv, const float* __restrict__ wS2s,
                            const float* __restrict__ wMvs2s) {
    const int idx = blockIdx.x * blockDim.x + threadIdx.x;
    if (idx < 2048) {
        const int l = idx & 31;
        const int s = idx >> 5;
        g_TSA[idx] = (l < 16) ? wLs[l * 64 + s] : wJLs[(l - 16) * 64 + s];
        g_TSB[idx] = (l < 16) ? wRs[l * 64 + s] : wJRs[(l - 16) * 64 + s];
        g_TS0[idx] = wS2mv[l * 64 + s];
        g_TW1[idx] = wS2s[l * 64 + s];
        g_TW2[idx] = wS2s[(32 + l) * 64 + s];
        if (idx < 1024) {
            const int c = idx >> 5;          // [c][o] layout, o = l
            g_TM1[idx] = wMvs2s[l * 32 + c];
            g_TM2[idx] = wMvs2s[(32 + l) * 32 + c];
        }
    }
}

// ---------------------------------------------------------------------------
// Main kernel: 12 warps, 4 tokens/warp (two packed pairs).
// Pass-split schedule keeps live registers under the 168/thread ceiling:
//   stage x -> A-pass (WA once, both pairs) -> B1 -> scalarS -> gp1/h1
//   -> B2 -> gp2/h2 -> output linear (WO once, both pairs) -> writes
// ---------------------------------------------------------------------------
#define NW 12
#define NTHREADS (NW * 32)

#define OFF_WA    0        // [32 i][9 b][32 lane]
#define OFF_WB    9216
#define OFF_WO    18432    // [32 c][9 b][32 o]
#define OFF_STG   27648
// Per-warp staging: TWO buffers of 32 rows x 32 floats (XOR-swizzled
// ulonglong2 slots), each reused for pair-interleaved x THEN hidden.
#define STG_PER_WARP (2 * 32 * 32)         // 2048 floats
#define SMEM_FLOATS (OFF_STG + NW * STG_PER_WARP)
#define SMEM_BYTES  (SMEM_FLOATS * 4)      // 208,896 B

__global__ void __launch_bounds__(NTHREADS, 1)
gb_kernel(const float* __restrict__ mv,      // [ntok][32][16]
          const float* __restrict__ refmv,   // [ntok][16]
          const float* __restrict__ scal,    // [ntok][64]
          const float* __restrict__ wLmv,
          const float* __restrict__ wRmv,
          const float* __restrict__ wJLmv,
          const float* __restrict__ wJRmv,
          const float* __restrict__ wOmv,    // [32 o][32 c][9 b]
          float* __restrict__ out,           // [ntok][32][16]
          float* __restrict__ outS,          // [ntok][64]
          int ntok)
{
    extern __shared__ float sm[];
    float* WA = sm + OFF_WA;
    float* WB = sm + OFF_WB;
    float* WO = sm + OFF_WO;

    const int tid  = threadIdx.x;
    const int lane = tid & 31;
    const int wid  = tid >> 5;

    // ---- stage mv weights (lane-permuted) ----
    // lane<16: A=left[lane], B=right[lane];  lane>=16: A=jl[l-16], B=jr[l-16]
    for (int idx = tid; idx < 9216; idx += NTHREADS) {
        const int l   = idx & 31;
        const int off = idx >> 5;               // i*9+b
        WA[idx] = (l < 16) ? wLmv[l * 288 + off] : wJLmv[(l - 16) * 288 + off];
        WB[idx] = (l < 16) ? wRmv[l * 288 + off] : wJRmv[(l - 16) * 288 + off];
        WO[idx] = wOmv[l * 288 + off];
    }
    __syncthreads();

    float* buf1 = sm + OFF_STG + wid * STG_PER_WARP; // pair1 staging (32x32, swizzled)
    float* buf2 = buf1 + 1024;                       // pair2 staging

    const int gw = blockIdx.x * NW + wid;
    const int nw = gridDim.x * NW;
    const int nquad = ntok >> 2;

    for (int q = gw; q < nquad; q += nw) {
        const int t0 = 4 * q;

        // ---- stage x for both pairs (pair-interleaved, swizzled rows) ----
        // Row i: logical ulonglong2 slot t holds blades (2t,2t+1) pairs;
        // physical slot = t ^ (i & 7).
        #pragma unroll
        for (int pp = 0; pp < 2; ++pp) {
            const float4* gxA = reinterpret_cast<const float4*>(mv + (size_t)(t0 + 2*pp)     * 512);
            const float4* gxB = reinterpret_cast<const float4*>(mv + (size_t)(t0 + 2*pp + 1) * 512);
            float* buf = pp ? buf2 : buf1;
            #pragma unroll
            for (int it = 0; it < 4; ++it) {
                const int c = it * 32 + lane;    // chunk 0..127
                const int i = c >> 2, qq = c & 3;
                const float4 a = gxA[c];
                const float4 b = gxB[c];
                const int m  = i & 7;
                const int p0 = (2 * qq) ^ m;
                const int p1 = p0 ^ 1;
                float* base = buf + i * 32;
                *reinterpret_cast<float4*>(base + p0 * 4) = make_float4(a.x, b.x, a.y, b.y);
                *reinterpret_cast<float4*>(base + p1 * 4) = make_float4(a.z, b.z, a.w, b.w);
            }
        }
        __syncwarp();

        // ---- A-pass: WA read once, applied to both pairs ----
        ull A1[16], A2[16];
        #pragma unroll
        for (int j = 0; j < 16; ++j) { A1[j] = 0ULL; A2[j] = 0ULL; }
        for (int i0 = 0; i0 < 32; i0 += 8) {
            #pragma unroll
            for (int k = 0; k < 8; ++k) {
                const int i = i0 + k;
                ull wa[9];
                #pragma unroll
                for (int b = 0; b < 9; ++b) wa[b] = dup2(WA[(i * 9 + b) * 32 + lane]);
                {
                    ull xr[16];
                    const float* base = buf1 + i * 32;
                    #pragma unroll
                    for (int t = 0; t < 8; ++t) {
                        const ulonglong2 v =
                            *reinterpret_cast<const ulonglong2*>(base + ((t ^ k) * 4));
                        xr[2*t] = v.x; xr[2*t+1] = v.y;
                    }
                    ga::linAcc2(A1, wa, xr);
                }
                {
                    ull xr[16];
                    const float* base = buf2 + i * 32;
                    #pragma unroll
                    for (int t = 0; t < 8; ++t) {
                        const ulonglong2 v =
                            *reinterpret_cast<const ulonglong2*>(base + ((t ^ k) * 4));
                        xr[2*t] = v.x; xr[2*t+1] = v.y;
                    }
                    ga::linAcc2(A2, wa, xr);
                }
            }
        }

        // ---- B-pass pair 1 ----
        ull B1[16];
        #pragma unroll
        for (int j = 0; j < 16; ++j) B1[j] = 0ULL;
        for (int i0 = 0; i0 < 32; i0 += 8) {
            #pragma unroll
            for (int k = 0; k < 8; ++k) {
                const int i = i0 + k;
                ull wb[9];
                #pragma unroll
                for (int b = 0; b < 9; ++b) wb[b] = dup2(WB[(i * 9 + b) * 32 + lane]);
                ull xr[16];
                const float* base = buf1 + i * 32;
                #pragma unroll
                for (int t = 0; t < 8; ++t) {
                    const ulonglong2 v =
                        *reinterpret_cast<const ulonglong2*>(base + ((t ^ k) * 4));
                    xr[2*t] = v.x; xr[2*t+1] = v.y;
                }
                ga::linAcc2(B1, wb, xr);
            }
        }

        // ---- scalar-head pass (global L1-resident tables, once per quad) ----
        float A0[4], B0[4], O0[4], s1[4], s2[4];
        #pragma unroll
        for (int t = 0; t < 4; ++t) { A0[t]=0.f; B0[t]=0.f; O0[t]=0.f; s1[t]=0.f; s2[t]=0.f; }
        #pragma unroll 4
        for (int s4 = 0; s4 < 16; ++s4) {
            float4 sv[4];
            #pragma unroll
            for (int t = 0; t < 4; ++t)
                sv[t] = __ldg(reinterpret_cast<const float4*>(scal + (size_t)(t0 + t) * 64) + s4);
            #pragma unroll
            for (int k = 0; k < 4; ++k) {
                const int s = s4 * 4 + k;
                const float wsa = g_TSA[s * 32 + lane];
                const float wsb = g_TSB[s * 32 + lane];
                const float wo0 = g_TS0[s * 32 + lane];
                const float w1  = g_TW1[s * 32 + lane];
                const float w2  = g_TW2[s * 32 + lane];
                #pragma unroll
                for (int t = 0; t < 4; ++t) {
                    const float x = (k == 0) ? sv[t].x : (k == 1) ? sv[t].y
                                   : (k == 2) ? sv[t].z : sv[t].w;
                    A0[t] = fmaf(wsa, x, A0[t]);
                    B0[t] = fmaf(wsb, x, B0[t]);
                    O0[t] = fmaf(wo0, x, O0[t]);
                    s1[t] = fmaf(w1,  x, s1[t]);
                    s2[t] = fmaf(w2,  x, s2[t]);
                }
            }
        }

        // ---- bilinear pair 1 -> h1 -> buf1 ----
        __syncwarp();   // all lanes done reading buf1
        {
            A1[0] = add2(A1[0], pack2(A0[0], A0[1]));
            B1[0] = add2(B1[0], pack2(B0[0], B0[1]));
            ull h[16];
            #pragma unroll
            for (int j = 0; j < 16; ++j) h[j] = 0ULL;
            if (lane < 16) {
                ga::gpAll(A1, B1, h, typename ga::mkseq<16>::type{});
            } else {
                const ull refp = pack2(refmv[(size_t)(t0)     * 16 + 15],
                                       refmv[(size_t)(t0 + 1) * 16 + 15]);
                ga::jnAll(A1, B1, h, typename ga::mkseq<16>::type{});
                #pragma unroll
                for (int j = 0; j < 16; ++j) h[j] = mul2(h[j], refp);
            }
            float* base = buf1 + lane * 32;
            const int m = lane & 7;
            #pragma unroll
            for (int t = 0; t < 8; ++t)
                *reinterpret_cast<ulonglong2*>(base + ((t ^ m) * 4)) =
                    make_ulonglong2(h[2*t], h[2*t+1]);
        }

        // ---- B-pass pair 2 ----
        ull B2[16];
        #pragma unroll
        for (int j = 0; j < 16; ++j) B2[j] = 0ULL;
        for (int i0 = 0; i0 < 32; i0 += 8) {
            #pragma unroll
            for (int k = 0; k < 8; ++k) {
                const int i = i0 + k;
                ull wb[9];
                #pragma unroll
                for (int b = 0; b < 9; ++b) wb[b] = dup2(WB[(i * 9 + b) * 32 + lane]);
                ull xr[16];
                const float* base = buf2 + i * 32;
                #pragma unroll
                for (int t = 0; t < 8; ++t) {
                    const ulonglong2 v =
                        *reinterpret_cast<const ulonglong2*>(base + ((t ^ k) * 4));
                    xr[2*t] = v.x; xr[2*t+1] = v.y;
                }
                ga::linAcc2(B2, wb, xr);
            }
        }

        // ---- bilinear pair 2 -> h2 -> buf2 ----
        __syncwarp();   // all lanes done reading buf2
        {
            A2[0] = add2(A2[0], pack2(A0[2], A0[3]));
            B2[0] = add2(B2[0], pack2(B0[2], B0[3]));
            ull h[16];
            #pragma unroll
            for (int j = 0; j < 16; ++j) h[j] = 0ULL;
            if (lane < 16) {
                ga::gpAll(A2, B2, h, typename ga::mkseq<16>::type{});
            } else {
                const ull refp = pack2(refmv[(size_t)(t0 + 2) * 16 + 15],
                                       refmv[(size_t)(t0 + 3) * 16 + 15]);
                ga::jnAll(A2, B2, h, typename ga::mkseq<16>::type{});
                #pragma unroll
                for (int j = 0; j < 16; ++j) h[j] = mul2(h[j], refp);
            }
            float* base = buf2 + lane * 32;
            const int m = lane & 7;
            #pragma unroll
            for (int t = 0; t < 8; ++t)
                *reinterpret_cast<ulonglong2*>(base + ((t ^ m) * 4)) =
                    make_ulonglong2(h[2*t], h[2*t+1]);
        }
        __syncwarp();

        // ---- output equi-linear + scalar heads: WO/WM once, both pairs ----
        ull O1[16], O2[16];
        O1[0] = pack2(O0[0], O0[1]);
        O2[0] = pack2(O0[2], O0[3]);
        #pragma unroll
        for (int j = 1; j < 16; ++j) { O1[j] = 0ULL; O2[j] = 0ULL; }
        ull os1p1 = pack2(s1[0], s1[1]), os2p1 = pack2(s2[0], s2[1]);
        ull os1p2 = pack2(s1[2], s1[3]), os2p2 = pack2(s2[2], s2[3]);

        for (int c0 = 0; c0 < 32; c0 += 8) {
            #pragma unroll
            for (int k = 0; k < 8; ++k) {
                const int c = c0 + k;
                ull wo[9];
                #pragma unroll
                for (int b = 0; b < 9; ++b) wo[b] = dup2(WO[(c * 9 + b) * 32 + lane]);
                const ull wm1 = dup2(g_TM1[c * 32 + lane]);
                const ull wm2 = dup2(g_TM2[c * 32 + lane]);
                {
                    ull hr[16];
                    const float* base = buf1 + c * 32;
                    #pragma unroll
                    for (int t = 0; t < 8; ++t) {
                        const ulonglong2 v =
                            *reinterpret_cast<const ulonglong2*>(base + ((t ^ k) * 4));
                        hr[2*t] = v.x; hr[2*t+1] = v.y;
                    }
                    ga::linAcc2(O1, wo, hr);
                    os1p1 = fma2(wm1, hr[0], os1p1);
                    os2p1 = fma2(wm2, hr[0], os2p1);
                }
                {
                    ull hr[16];
                    const float* base = buf2 + c * 32;
                    #pragma unroll
                    for (int t = 0; t < 8; ++t) {
                        const ulonglong2 v =
                            *reinterpret_cast<const ulonglong2*>(base + ((t ^ k) * 4));
                        hr[2*t] = v.x; hr[2*t+1] = v.y;
                    }
                    ga::linAcc2(O2, wo, hr);
                    os1p2 = fma2(wm1, hr[0], os1p2);
                    os2p2 = fma2(wm2, hr[0], os2p2);
                }
            }
        }

        // ---- write outputs ----
        #pragma unroll
        for (int pp = 0; pp < 2; ++pp) {
            const ull* Op = pp ? O2 : O1;
            float Oa[16], Ob[16];
            #pragma unroll
            for (int j = 0; j < 16; ++j) unpack2(Op[j], Oa[j], Ob[j]);
            float* omA = out + (size_t)(t0 + 2*pp)     * 512 + lane * 16;
            float* omB = out + (size_t)(t0 + 2*pp + 1) * 512 + lane * 16;
            #pragma unroll
            for (int m = 0; m < 4; ++m) {
                *reinterpret_cast<float4*>(omA + m * 4) =
                    make_float4(Oa[m*4+0], Oa[m*4+1], Oa[m*4+2], Oa[m*4+3]);
                *reinterpret_cast<float4*>(omB + m * 4) =
                    make_float4(Ob[m*4+0], Ob[m*4+1], Ob[m*4+2], Ob[m*4+3]);
            }
        }
        {
            float a1, b1, a2, b2;
            unpack2(os1p1, a1, b1); unpack2(os2p1, a2, b2);
            outS[(size_t)(t0)     * 64 + lane]      = a1;
            outS[(size_t)(t0)     * 64 + 32 + lane] = a2;
            outS[(size_t)(t0 + 1) * 64 + lane]      = b1;
            outS[(size_t)(t0 + 1) * 64 + 32 + lane] = b2;
            unpack2(os1p2, a1, b1); unpack2(os2p2, a2, b2);
            outS[(size_t)(t0 + 2) * 64 + lane]      = a1;
            outS[(size_t)(t0 + 2) * 64 + 32 + lane] = a2;
            outS[(size_t)(t0 + 3) * 64 + lane]      = b1;
            outS[(size_t)(t0 + 3) * 64 + 32 + lane] = b2;
        }
        __syncwarp();   // staging reused next iteration
    }
}

// ---------------------------------------------------------------------------
// Launch
// ---------------------------------------------------------------------------
extern "C" void kernel_launch(void* const* d_in, const int* in_sizes, int n_in,
                              void* d_out, int out_size) {
    const float* mv     = (const float*)d_in[0];
    const float* refmv  = (const float*)d_in[1];
    const float* scal   = (const float*)d_in[2];
    // d_in[3..5] = basis, gp, jn (structure hardcoded at compile time)
    const float* wLmv   = (const float*)d_in[6];
    const float* wLs    = (const float*)d_in[7];
    const float* wRmv   = (const float*)d_in[8];
    const float* wRs    = (const float*)d_in[9];
    const float* wJLmv  = (const float*)d_in[10];
    const float* wJLs   = (const float*)d_in[11];
    const float* wJRmv  = (const float*)d_in[12];
    const float* wJRs   = (const float*)d_in[13];
    const float* wOmv   = (const float*)d_in[14];
    const float* wS2mv  = (const float*)d_in[15];
    const float* wMvs2s = (const float*)d_in[16];
    const float* wS2s   = (const float*)d_in[17];

    const int ntok = in_sizes[0] / 512;          // 32768
    float* out  = (float*)d_out;                 // [ntok*512] out_mv
    float* outS = out + (size_t)ntok * 512;      // [ntok*64]  out_s

    int dev = 0;
    cudaGetDevice(&dev);
    int nsm = 148;
    cudaDeviceGetAttribute(&nsm, cudaDevAttrMultiProcessorCount, dev);

    init_tables<<<8, 256>>>(wLs, wRs, wJLs, wJRs, wS2mv, wS2s, wMvs2s);

    cudaFuncSetAttribute(gb_kernel, cudaFuncAttributeMaxDynamicSharedMemorySize, SMEM_BYTES);
    gb_kernel<<<nsm, NTHREADS, SMEM_BYTES>>>(
        mv, refmv, scal,
        wLmv, wRmv, wJLmv, wJRmv, wOmv,
        out, outS, ntok);
}

// round 11
// speedup vs baseline: 1.9067x; 1.9067x over previous
#include <cuda_runtime.h>
#include <cstdint>
#include <cstddef>

typedef unsigned long long ull;

// ---------------------------------------------------------------------------
// Packed f32x2 helpers (SASS FFMA2 path — only reachable via explicit PTX)
// ---------------------------------------------------------------------------
__device__ __forceinline__ ull fma2(ull a, ull b, ull c) {
    ull d; asm("fma.rn.f32x2 %0,%1,%2,%3;" : "=l"(d) : "l"(a), "l"(b), "l"(c)); return d;
}
__device__ __forceinline__ ull mul2(ull a, ull b) {
    ull d; asm("mul.rn.f32x2 %0,%1,%2;" : "=l"(d) : "l"(a), "l"(b)); return d;
}
__device__ __forceinline__ ull pack2(float lo, float hi) {
    ull d; asm("mov.b64 %0,{%1,%2};" : "=l"(d) : "f"(lo), "f"(hi)); return d;
}
__device__ __forceinline__ ull dup2(float x) {
    ull d; asm("mov.b64 %0,{%1,%1};" : "=l"(d) : "f"(x)); return d;
}
__device__ __forceinline__ void unpack2(ull a, float& lo, float& hi) {
    asm("mov.b64 {%0,%1},%2;" : "=f"(lo), "=f"(hi) : "l"(a));
}
__device__ __forceinline__ ull neg2(ull a) { return a ^ 0x8000000080000000ULL; }

// ---------------------------------------------------------------------------
// Compile-time PGA(3,0,1) tables. Blade order matches the reference:
// idx : (), e0,e1,e2,e3, e01,e02,e03,e12,e13,e23, e012,e013,e023,e123, e0123
// ---------------------------------------------------------------------------
namespace ga {

__host__ __device__ constexpr unsigned bladeMask(int i) {
    constexpr unsigned m[16] = {0u,1u,2u,4u,8u, 3u,5u,9u,6u,10u,12u, 7u,11u,13u,14u, 15u};
    return m[i];
}
__host__ __device__ constexpr int idxOfMask(unsigned m) {
    constexpr int t[16] = {0,1,2,5,3,6,8,11,4,7,9,12,10,13,14,15};
    return t[m];
}
__host__ __device__ constexpr int invCnt(unsigned a, unsigned b) {
    int s = 0;
    for (int i = 0; i < 4; ++i)
        if ((b >> i) & 1u)
            for (int j = i + 1; j < 4; ++j)
                if ((a >> j) & 1u) ++s;
    return s;
}
__host__ __device__ constexpr float gpSign(int j, int k) {
    unsigned a = bladeMask(j), b = bladeMask(k);
    if (a & b & 1u) return 0.0f;                   // e0*e0 = 0
    return (invCnt(a, b) & 1) ? -1.0f : 1.0f;
}
__host__ __device__ constexpr int gpTgt(int j, int k) {
    return idxOfMask(bladeMask(j) ^ bladeMask(k));
}
__host__ __device__ constexpr float dSign(int t) {
    unsigned m = bladeMask(t);
    return (invCnt(m, 15u ^ m) & 1) ? -1.0f : 1.0f;
}
__host__ __device__ constexpr float jnCoef(int b, int c) {
    unsigned mb = bladeMask(b), mc = bladeMask(c);
    if ((mb | mc) != 15u) return 0.0f;
    unsigned ma = mb & mc;
    int ia = idxOfMask(15u ^ ma);
    unsigned cb = 15u ^ mb, cc = 15u ^ mc;
    float so = (invCnt(cb, cc) & 1) ? -1.0f : 1.0f;
    return dSign(ia) * so * dSign(b) * dSign(c);
}
__host__ __device__ constexpr int jnTgt(int b, int c) {
    return idxOfMask(bladeMask(b) & bladeMask(c));
}

template<int...> struct iseq {};
template<int N, int... S> struct mkseq : mkseq<N-1, N-1, S...> {};
template<int... S> struct mkseq<0, S...> { using type = iseq<S...>; };

// Row-local negation: only neg2(L[J]) for the CURRENT row is live.
template<int J, int K>
__device__ __forceinline__ void gpTerm(ull aj, ull naj, const ull (&R)[16], ull (&h)[16]) {
    constexpr float s = gpSign(J, K);
    if constexpr (s > 0.5f) {
        constexpr int t = gpTgt(J, K);
        h[t] = fma2(aj, R[K], h[t]);
    } else if constexpr (s < -0.5f) {
        constexpr int t = gpTgt(J, K);
        h[t] = fma2(naj, R[K], h[t]);
    }
}
template<int J, int... Ks>
__device__ __forceinline__ void gpRow(const ull (&L)[16], const ull (&R)[16],
                                      ull (&h)[16], iseq<Ks...>) {
    const ull aj  = L[J];
    const ull naj = neg2(aj);
    (gpTerm<J, Ks>(aj, naj, R, h), ...);
}
template<int... Js>
__device__ __forceinline__ void gpAll(const ull (&L)[16], const ull (&R)[16],
                                      ull (&h)[16], iseq<Js...>) {
    (gpRow<Js>(L, R, h, typename mkseq<16>::type{}), ...);
}

template<int J, int K>
__device__ __forceinline__ void jnTerm(ull aj, ull naj, const ull (&R)[16], ull (&h)[16]) {
    constexpr float s = jnCoef(J, K);
    if constexpr (s > 0.5f) {
        constexpr int t = jnTgt(J, K);
        h[t] = fma2(aj, R[K], h[t]);
    } else if constexpr (s < -0.5f) {
        constexpr int t = jnTgt(J, K);
        h[t] = fma2(naj, R[K], h[t]);
    }
}
template<int J, int... Ks>
__device__ __forceinline__ void jnRow(const ull (&L)[16], const ull (&R)[16],
                                      ull (&h)[16], iseq<Ks...>) {
    const ull aj  = L[J];
    const ull naj = neg2(aj);
    (jnTerm<J, Ks>(aj, naj, R, h), ...);
}
template<int... Js>
__device__ __forceinline__ void jnAll(const ull (&L)[16], const ull (&R)[16],
                                      ull (&h)[16], iseq<Js...>) {
    (jnRow<Js>(L, R, h, typename mkseq<16>::type{}), ...);
}

// Equivariant-linear accumulation (packed pair), one input channel.
// grades = [0,1,1,1,1, 2,2,2,2,2,2, 3,3,3,3, 4]
// e0 wedge (+1): 1<-0 (w5); 5,6,7<-2,3,4 (w6); 11,12,13<-8,9,10 (w7); 15<-14 (w8)
__device__ __forceinline__ void linAcc2(ull (&o)[16], const ull (&w)[9], const ull (&x)[16]) {
    o[0]  = fma2(w[0], x[0],  o[0]);
    o[1]  = fma2(w[1], x[1],  o[1]);  o[1]  = fma2(w[5], x[0],  o[1]);
    o[2]  = fma2(w[1], x[2],  o[2]);
    o[3]  = fma2(w[1], x[3],  o[3]);
    o[4]  = fma2(w[1], x[4],  o[4]);
    o[5]  = fma2(w[2], x[5],  o[5]);  o[5]  = fma2(w[6], x[2],  o[5]);
    o[6]  = fma2(w[2], x[6],  o[6]);  o[6]  = fma2(w[6], x[3],  o[6]);
    o[7]  = fma2(w[2], x[7],  o[7]);  o[7]  = fma2(w[6], x[4],  o[7]);
    o[8]  = fma2(w[2], x[8],  o[8]);
    o[9]  = fma2(w[2], x[9],  o[9]);
    o[10] = fma2(w[2], x[10], o[10]);
    o[11] = fma2(w[3], x[11], o[11]); o[11] = fma2(w[7], x[8],  o[11]);
    o[12] = fma2(w[3], x[12], o[12]); o[12] = fma2(w[7], x[9],  o[12]);
    o[13] = fma2(w[3], x[13], o[13]); o[13] = fma2(w[7], x[10], o[13]);
    o[14] = fma2(w[3], x[14], o[14]);
    o[15] = fma2(w[4], x[15], o[15]); o[15] = fma2(w[8], x[14], o[15]);
}

} // namespace ga

// ---------------------------------------------------------------------------
// Precomputed scalar-head results: P[tok][160] =
//   [0:32)=A0, [32:64)=B0, [64:96)=O0, [96:128)=s1, [128:160)=s2
// Produced by scalar_head_kernel (a [ntok,64]x[64,160] matmul), consumed by
// the main kernel as 10 coalesced floats per token pair.
// ---------------------------------------------------------------------------
#define MAX_TOK 32768
__device__ float g_P[MAX_TOK * 160];

__global__ void __launch_bounds__(256, 1)
scalar_head_kernel(const float* __restrict__ scal,
                   const float* __restrict__ wLs, const float* __restrict__ wRs,
                   const float* __restrict__ wJLs, const float* __restrict__ wJRs,
                   const float* __restrict__ wS2mv, const float* __restrict__ wS2s,
                   int ntok)
{
    __shared__ float T[64 * 160];          // 40 KB: [s][component]
    const int tid = threadIdx.x;
    for (int idx = tid; idx < 64 * 160; idx += 256) {
        const int s = idx / 160;
        const int c = idx - s * 160;
        const int g = c >> 5;
        const int k = c & 31;
        float v;
        if (g == 0)      v = (k < 16) ? wLs[k * 64 + s] : wJLs[(k - 16) * 64 + s];
        else if (g == 1) v = (k < 16) ? wRs[k * 64 + s] : wJRs[(k - 16) * 64 + s];
        else if (g == 2) v = wS2mv[k * 64 + s];
        else if (g == 3) v = wS2s[k * 64 + s];
        else             v = wS2s[(32 + k) * 64 + s];
        T[idx] = v;
    }
    __syncthreads();

    const int lane = tid & 31;
    const int wid  = tid >> 5;
    const int nwarps = gridDim.x * 8;
    const int noct = (ntok + 7) >> 3;      // token octets

    for (int o = blockIdx.x * 8 + wid; o < noct; o += nwarps) {
        const int t0 = o * 8;
        float acc[5][8];
        #pragma unroll
        for (int g = 0; g < 5; ++g)
            #pragma unroll
            for (int t = 0; t < 8; ++t) acc[g][t] = 0.0f;

        for (int s4 = 0; s4 < 16; ++s4) {
            float4 sv[8];
            #pragma unroll
            for (int t = 0; t < 8; ++t) {
                const int tk = t0 + t;
                sv[t] = (tk < ntok)
                    ? __ldg(reinterpret_cast<const float4*>(scal + (size_t)tk * 64) + s4)
                    : make_float4(0.f, 0.f, 0.f, 0.f);
            }
            #pragma unroll
            for (int k = 0; k < 4; ++k) {
                const int s = s4 * 4 + k;
                const float w0 = T[s * 160 +   0 + lane];
                const float w1 = T[s * 160 +  32 + lane];
                const float w2 = T[s * 160 +  64 + lane];
                const float w3 = T[s * 160 +  96 + lane];
                const float w4 = T[s * 160 + 128 + lane];
                #pragma unroll
                for (int t = 0; t < 8; ++t) {
                    const float x = (k == 0) ? sv[t].x : (k == 1) ? sv[t].y
                                   : (k == 2) ? sv[t].z : sv[t].w;
                    acc[0][t] = fmaf(w0, x, acc[0][t]);
                    acc[1][t] = fmaf(w1, x, acc[1][t]);
                    acc[2][t] = fmaf(w2, x, acc[2][t]);
                    acc[3][t] = fmaf(w3, x, acc[3][t]);
                    acc[4][t] = fmaf(w4, x, acc[4][t]);
                }
            }
        }
        #pragma unroll
        for (int t = 0; t < 8; ++t) {
            const int tk = t0 + t;
            if (tk < ntok) {
                #pragma unroll
                for (int g = 0; g < 5; ++g)
                    g_P[(size_t)tk * 160 + g * 32 + lane] = acc[g][t];
            }
        }
    }
}

// ---------------------------------------------------------------------------
// Main kernel: 12 warps, token pair per warp (R6 structure, scalar head
// hoisted out, row-local negation in gp/jn).
// ---------------------------------------------------------------------------
#define NW 12
#define NTHREADS (NW * 32)

#define OFF_WA    0        // [32 i][9 b][32 lane]
#define OFF_WB    9216
#define OFF_WO    18432    // [32 c][9 b][32 o]
#define OFF_WM1   27648    // [32 c][32 o]
#define OFF_WM2   28672
#define OFF_STG   29696
// Per-warp staging: 32 rows x 32 floats (XOR-swizzled ulonglong2 slots),
// reused for pair-interleaved x THEN hidden.
#define STG_PER_WARP 1024
#define SMEM_FLOATS (OFF_STG + NW * STG_PER_WARP)
#define SMEM_BYTES  (SMEM_FLOATS * 4)      // 167,936 B

__global__ void __launch_bounds__(NTHREADS, 1)
gb_kernel(const float* __restrict__ mv,      // [ntok][32][16]
          const float* __restrict__ refmv,   // [ntok][16]
          const float* __restrict__ wLmv,
          const float* __restrict__ wRmv,
          const float* __restrict__ wJLmv,
          const float* __restrict__ wJRmv,
          const float* __restrict__ wOmv,    // [32 o][32 c][9 b]
          const float* __restrict__ wMvs2s,  // [64 o][32 c]
          float* __restrict__ out,           // [ntok][32][16]
          float* __restrict__ outS,          // [ntok][64]
          int ntok)
{
    extern __shared__ float sm[];
    float* WA  = sm + OFF_WA;
    float* WB  = sm + OFF_WB;
    float* WO  = sm + OFF_WO;
    float* WM1 = sm + OFF_WM1;
    float* WM2 = sm + OFF_WM2;

    const int tid  = threadIdx.x;
    const int lane = tid & 31;
    const int wid  = tid >> 5;

    // ---- stage mv weights (lane-permuted) ----
    // lane<16: A=left[lane], B=right[lane];  lane>=16: A=jl[l-16], B=jr[l-16]
    for (int idx = tid; idx < 9216; idx += NTHREADS) {
        const int l   = idx & 31;
        const int off = idx >> 5;               // i*9+b
        WA[idx] = (l < 16) ? wLmv[l * 288 + off] : wJLmv[(l - 16) * 288 + off];
        WB[idx] = (l < 16) ? wRmv[l * 288 + off] : wJRmv[(l - 16) * 288 + off];
        WO[idx] = wOmv[l * 288 + off];
    }
    for (int idx = tid; idx < 1024; idx += NTHREADS) {
        const int l = idx & 31;
        const int c = idx >> 5;
        WM1[idx] = wMvs2s[l * 32 + c];
        WM2[idx] = wMvs2s[(32 + l) * 32 + c];
    }
    __syncthreads();

    float* buf = sm + OFF_STG + wid * STG_PER_WARP; // 32 rows x 32 floats (swizzled)

    const int gw = blockIdx.x * NW + wid;
    const int nw = gridDim.x * NW;
    const int npair = ntok >> 1;

    for (int p = gw; p < npair; p += nw) {
        const int tA = 2 * p, tB = 2 * p + 1;

        // ---- stage token-pair inputs ----
        // Row i: logical ulonglong2 slot t holds blades (2t, 2t+1) pairs;
        // physical slot = t ^ (i & 7).
        const float4* gxA = reinterpret_cast<const float4*>(mv + (size_t)tA * 512);
        const float4* gxB = reinterpret_cast<const float4*>(mv + (size_t)tB * 512);
        #pragma unroll
        for (int it = 0; it < 4; ++it) {
            const int c = it * 32 + lane;        // chunk 0..127
            const int i = c >> 2, q = c & 3;     // channel, quarter (blades 4q..4q+3)
            const float4 a = gxA[c];
            const float4 b = gxB[c];
            const int m  = i & 7;
            const int p0 = (2 * q) ^ m;          // slot for blades 4q,4q+1
            const int p1 = p0 ^ 1;               // slot for blades 4q+2,4q+3
            float* base = buf + i * 32;
            *reinterpret_cast<float4*>(base + p0 * 4) = make_float4(a.x, b.x, a.y, b.y);
            *reinterpret_cast<float4*>(base + p1 * 4) = make_float4(a.z, b.z, a.w, b.w);
        }
        const ull refp = pack2(refmv[(size_t)tA * 16 + 15], refmv[(size_t)tB * 16 + 15]);
        const float* Pa = g_P + (size_t)tA * 160;
        const float* Pb = g_P + (size_t)tB * 160;
        __syncwarp();

        // ---- input equi-linears owned by this lane (packed pair) ----
        ull A[16], Bv[16];
        A[0]  = pack2(__ldg(Pa + lane),      __ldg(Pb + lane));
        Bv[0] = pack2(__ldg(Pa + 32 + lane), __ldg(Pb + 32 + lane));
        #pragma unroll
        for (int j = 1; j < 16; ++j) { A[j] = 0ULL; Bv[j] = 0ULL; }

        for (int i0 = 0; i0 < 32; i0 += 8) {
            #pragma unroll
            for (int k = 0; k < 8; ++k) {
                const int i = i0 + k;
                ull xr[16];
                const float* base = buf + i * 32;
                #pragma unroll
                for (int t = 0; t < 8; ++t) {    // broadcast reads, swizzled slots
                    const ulonglong2 v =
                        *reinterpret_cast<const ulonglong2*>(base + ((t ^ k) * 4));
                    xr[2*t] = v.x; xr[2*t+1] = v.y;
                }
                ull wa[9], wb[9];
                #pragma unroll
                for (int b = 0; b < 9; ++b) {
                    wa[b] = dup2(WA[(i * 9 + b) * 32 + lane]);
                    wb[b] = dup2(WB[(i * 9 + b) * 32 + lane]);
                }
                ga::linAcc2(A, wa, xr);
                ga::linAcc2(Bv, wb, xr);
            }
        }
        __syncwarp();   // all lanes done reading x staging

        // ---- bilinear: gp on lanes 0..15, join on lanes 16..31 ----
        ull h[16];
        #pragma unroll
        for (int j = 0; j < 16; ++j) h[j] = 0ULL;
        if (lane < 16) {
            ga::gpAll(A, Bv, h, typename ga::mkseq<16>::type{});
        } else {
            ga::jnAll(A, Bv, h, typename ga::mkseq<16>::type{});
            #pragma unroll
            for (int j = 0; j < 16; ++j) h[j] = mul2(h[j], refp);
        }
        // stage hidden (lane = channel) into the SAME buffer, swizzled
        {
            float* base = buf + lane * 32;
            const int m = lane & 7;
            #pragma unroll
            for (int t = 0; t < 8; ++t)
                *reinterpret_cast<ulonglong2*>(base + ((t ^ m) * 4)) =
                    make_ulonglong2(h[2*t], h[2*t+1]);
        }
        __syncwarp();

        // ---- output equi-linear + scalar heads: lane = output channel o ----
        ull O[16];
        O[0] = pack2(__ldg(Pa + 64 + lane), __ldg(Pb + 64 + lane));
        #pragma unroll
        for (int j = 1; j < 16; ++j) O[j] = 0ULL;
        ull os1 = pack2(__ldg(Pa + 96 + lane),  __ldg(Pb + 96 + lane));
        ull os2 = pack2(__ldg(Pa + 128 + lane), __ldg(Pb + 128 + lane));

        for (int c0 = 0; c0 < 32; c0 += 8) {
            #pragma unroll
            for (int k = 0; k < 8; ++k) {
                const int c = c0 + k;
                ull hr[16];
                const float* base = buf + c * 32;
                #pragma unroll
                for (int t = 0; t < 8; ++t) {    // broadcast reads, swizzled slots
                    const ulonglong2 v =
                        *reinterpret_cast<const ulonglong2*>(base + ((t ^ k) * 4));
                    hr[2*t] = v.x; hr[2*t+1] = v.y;
                }
                ull wo[9];
                #pragma unroll
                for (int b = 0; b < 9; ++b) wo[b] = dup2(WO[(c * 9 + b) * 32 + lane]);
                ga::linAcc2(O, wo, hr);

                os1 = fma2(dup2(WM1[c * 32 + lane]), hr[0], os1);
                os2 = fma2(dup2(WM2[c * 32 + lane]), hr[0], os2);
            }
        }

        // ---- write outputs ----
        {
            float Oa[16], Ob[16];
            #pragma unroll
            for (int j = 0; j < 16; ++j) unpack2(O[j], Oa[j], Ob[j]);
            float* omA = out + (size_t)tA * 512 + lane * 16;
            float* omB = out + (size_t)tB * 512 + lane * 16;
            #pragma unroll
            for (int m = 0; m < 4; ++m) {
                *reinterpret_cast<float4*>(omA + m * 4) =
                    make_float4(Oa[m*4+0], Oa[m*4+1], Oa[m*4+2], Oa[m*4+3]);
                *reinterpret_cast<float4*>(omB + m * 4) =
                    make_float4(Ob[m*4+0], Ob[m*4+1], Ob[m*4+2], Ob[m*4+3]);
            }
        }
        {
            float a1, b1, a2, b2;
            unpack2(os1, a1, b1);
            unpack2(os2, a2, b2);
            outS[(size_t)tA * 64 + lane]      = a1;
            outS[(size_t)tA * 64 + 32 + lane] = a2;
            outS[(size_t)tB * 64 + lane]      = b1;
            outS[(size_t)tB * 64 + 32 + lane] = b2;
        }
        __syncwarp();   // staging reused next iteration
    }
}

// ---------------------------------------------------------------------------
// Launch
// ---------------------------------------------------------------------------
extern "C" void kernel_launch(void* const* d_in, const int* in_sizes, int n_in,
                              void* d_out, int out_size) {
    const float* mv     = (const float*)d_in[0];
    const float* refmv  = (const float*)d_in[1];
    const float* scal   = (const float*)d_in[2];
    // d_in[3..5] = basis, gp, jn (structure hardcoded at compile time)
    const float* wLmv   = (const float*)d_in[6];
    const float* wLs    = (const float*)d_in[7];
    const float* wRmv   = (const float*)d_in[8];
    const float* wRs    = (const float*)d_in[9];
    const float* wJLmv  = (const float*)d_in[10];
    const float* wJLs   = (const float*)d_in[11];
    const float* wJRmv  = (const float*)d_in[12];
    const float* wJRs   = (const float*)d_in[13];
    const float* wOmv   = (const float*)d_in[14];
    const float* wS2mv  = (const float*)d_in[15];
    const float* wMvs2s = (const float*)d_in[16];
    const float* wS2s   = (const float*)d_in[17];

    const int ntok = in_sizes[0] / 512;          // 32768
    float* out  = (float*)d_out;                 // [ntok*512] out_mv
    float* outS = out + (size_t)ntok * 512;      // [ntok*64]  out_s

    int dev = 0;
    cudaGetDevice(&dev);
    int nsm = 148;
    cudaDeviceGetAttribute(&nsm, cudaDevAttrMultiProcessorCount, dev);

    // Stage 1: scalar-head precompute ([ntok,64] @ [64,160] -> g_P)
    const int noct = (ntok + 7) / 8;             // token octets (8 tokens/warp)
    int nblk = (noct + 7) / 8;                   // 8 warps per block
    if (nblk > 2048) nblk = 2048;
    scalar_head_kernel<<<nblk, 256>>>(scal, wLs, wRs, wJLs, wJRs, wS2mv, wS2s, ntok);

    // Stage 2: main geometric-bilinear kernel
    cudaFuncSetAttribute(gb_kernel, cudaFuncAttributeMaxDynamicSharedMemorySize, SMEM_BYTES);
    gb_kernel<<<nsm, NTHREADS, SMEM_BYTES>>>(
        mv, refmv,
        wLmv, wRmv, wJLmv, wJRmv, wOmv, wMvs2s,
        out, outS, ntok);
}

// round 12
// speedup vs baseline: 2.0655x; 1.0833x over previous
#include <cuda_runtime.h>
#include <cstdint>
#include <cstddef>

typedef unsigned long long ull;

// ---------------------------------------------------------------------------
// Packed f32x2 helpers (SASS FFMA2 path — only reachable via explicit PTX)
// ---------------------------------------------------------------------------
__device__ __forceinline__ ull fma2(ull a, ull b, ull c) {
    ull d; asm("fma.rn.f32x2 %0,%1,%2,%3;" : "=l"(d) : "l"(a), "l"(b), "l"(c)); return d;
}
__device__ __forceinline__ ull mul2(ull a, ull b) {
    ull d; asm("mul.rn.f32x2 %0,%1,%2;" : "=l"(d) : "l"(a), "l"(b)); return d;
}
__device__ __forceinline__ ull pack2(float lo, float hi) {
    ull d; asm("mov.b64 %0,{%1,%2};" : "=l"(d) : "f"(lo), "f"(hi)); return d;
}
__device__ __forceinline__ ull dup2(float x) {
    ull d; asm("mov.b64 %0,{%1,%1};" : "=l"(d) : "f"(x)); return d;
}
__device__ __forceinline__ void unpack2(ull a, float& lo, float& hi) {
    asm("mov.b64 {%0,%1},%2;" : "=f"(lo), "=f"(hi) : "l"(a));
}
__device__ __forceinline__ ull neg2(ull a) { return a ^ 0x8000000080000000ULL; }

// ---------------------------------------------------------------------------
// Compile-time PGA(3,0,1) tables. Blade order matches the reference:
// idx : (), e0,e1,e2,e3, e01,e02,e03,e12,e13,e23, e012,e013,e023,e123, e0123
// ---------------------------------------------------------------------------
namespace ga {

__host__ __device__ constexpr unsigned bladeMask(int i) {
    constexpr unsigned m[16] = {0u,1u,2u,4u,8u, 3u,5u,9u,6u,10u,12u, 7u,11u,13u,14u, 15u};
    return m[i];
}
__host__ __device__ constexpr int idxOfMask(unsigned m) {
    constexpr int t[16] = {0,1,2,5,3,6,8,11,4,7,9,12,10,13,14,15};
    return t[m];
}
__host__ __device__ constexpr int invCnt(unsigned a, unsigned b) {
    int s = 0;
    for (int i = 0; i < 4; ++i)
        if ((b >> i) & 1u)
            for (int j = i + 1; j < 4; ++j)
                if ((a >> j) & 1u) ++s;
    return s;
}
__host__ __device__ constexpr float gpSign(int j, int k) {
    unsigned a = bladeMask(j), b = bladeMask(k);
    if (a & b & 1u) return 0.0f;                   // e0*e0 = 0
    return (invCnt(a, b) & 1) ? -1.0f : 1.0f;
}
__host__ __device__ constexpr int gpTgt(int j, int k) {
    return idxOfMask(bladeMask(j) ^ bladeMask(k));
}
__host__ __device__ constexpr float dSign(int t) {
    unsigned m = bladeMask(t);
    return (invCnt(m, 15u ^ m) & 1) ? -1.0f : 1.0f;
}
__host__ __device__ constexpr float jnCoef(int b, int c) {
    unsigned mb = bladeMask(b), mc = bladeMask(c);
    if ((mb | mc) != 15u) return 0.0f;
    unsigned ma = mb & mc;
    int ia = idxOfMask(15u ^ ma);
    unsigned cb = 15u ^ mb, cc = 15u ^ mc;
    float so = (invCnt(cb, cc) & 1) ? -1.0f : 1.0f;
    return dSign(ia) * so * dSign(b) * dSign(c);
}
__host__ __device__ constexpr int jnTgt(int b, int c) {
    return idxOfMask(bladeMask(b) & bladeMask(c));
}

template<int...> struct iseq {};
template<int N, int... S> struct mkseq : mkseq<N-1, N-1, S...> {};
template<int... S> struct mkseq<0, S...> { using type = iseq<S...>; };

// Row-local negation: only neg2(L[J]) for the CURRENT row is live.
template<int J, int K>
__device__ __forceinline__ void gpTerm(ull aj, ull naj, const ull (&R)[16], ull (&h)[16]) {
    constexpr float s = gpSign(J, K);
    if constexpr (s > 0.5f) {
        constexpr int t = gpTgt(J, K);
        h[t] = fma2(aj, R[K], h[t]);
    } else if constexpr (s < -0.5f) {
        constexpr int t = gpTgt(J, K);
        h[t] = fma2(naj, R[K], h[t]);
    }
}
template<int J, int... Ks>
__device__ __forceinline__ void gpRow(const ull (&L)[16], const ull (&R)[16],
                                      ull (&h)[16], iseq<Ks...>) {
    const ull aj  = L[J];
    const ull naj = neg2(aj);
    (gpTerm<J, Ks>(aj, naj, R, h), ...);
}
template<int... Js>
__device__ __forceinline__ void gpAll(const ull (&L)[16], const ull (&R)[16],
                                      ull (&h)[16], iseq<Js...>) {
    (gpRow<Js>(L, R, h, typename mkseq<16>::type{}), ...);
}

template<int J, int K>
__device__ __forceinline__ void jnTerm(ull aj, ull naj, const ull (&R)[16], ull (&h)[16]) {
    constexpr float s = jnCoef(J, K);
    if constexpr (s > 0.5f) {
        constexpr int t = jnTgt(J, K);
        h[t] = fma2(aj, R[K], h[t]);
    } else if constexpr (s < -0.5f) {
        constexpr int t = jnTgt(J, K);
        h[t] = fma2(naj, R[K], h[t]);
    }
}
template<int J, int... Ks>
__device__ __forceinline__ void jnRow(const ull (&L)[16], const ull (&R)[16],
                                      ull (&h)[16], iseq<Ks...>) {
    const ull aj  = L[J];
    const ull naj = neg2(aj);
    (jnTerm<J, Ks>(aj, naj, R, h), ...);
}
template<int... Js>
__device__ __forceinline__ void jnAll(const ull (&L)[16], const ull (&R)[16],
                                      ull (&h)[16], iseq<Js...>) {
    (jnRow<Js>(L, R, h, typename mkseq<16>::type{}), ...);
}

// Equivariant-linear accumulation (packed pair), one input channel.
// grades = [0,1,1,1,1, 2,2,2,2,2,2, 3,3,3,3, 4]
// e0 wedge (+1): 1<-0 (w5); 5,6,7<-2,3,4 (w6); 11,12,13<-8,9,10 (w7); 15<-14 (w8)
__device__ __forceinline__ void linAcc2(ull (&o)[16], const ull (&w)[9], const ull (&x)[16]) {
    o[0]  = fma2(w[0], x[0],  o[0]);
    o[1]  = fma2(w[1], x[1],  o[1]);  o[1]  = fma2(w[5], x[0],  o[1]);
    o[2]  = fma2(w[1], x[2],  o[2]);
    o[3]  = fma2(w[1], x[3],  o[3]);
    o[4]  = fma2(w[1], x[4],  o[4]);
    o[5]  = fma2(w[2], x[5],  o[5]);  o[5]  = fma2(w[6], x[2],  o[5]);
    o[6]  = fma2(w[2], x[6],  o[6]);  o[6]  = fma2(w[6], x[3],  o[6]);
    o[7]  = fma2(w[2], x[7],  o[7]);  o[7]  = fma2(w[6], x[4],  o[7]);
    o[8]  = fma2(w[2], x[8],  o[8]);
    o[9]  = fma2(w[2], x[9],  o[9]);
    o[10] = fma2(w[2], x[10], o[10]);
    o[11] = fma2(w[3], x[11], o[11]); o[11] = fma2(w[7], x[8],  o[11]);
    o[12] = fma2(w[3], x[12], o[12]); o[12] = fma2(w[7], x[9],  o[12]);
    o[13] = fma2(w[3], x[13], o[13]); o[13] = fma2(w[7], x[10], o[13]);
    o[14] = fma2(w[3], x[14], o[14]);
    o[15] = fma2(w[4], x[15], o[15]); o[15] = fma2(w[8], x[14], o[15]);
}

} // namespace ga

// ---------------------------------------------------------------------------
// Stage-0/1 global scratch.
// g_T[64 s][160 c]: pre-transposed scalar-head weights
//   c = g*32+k: g0=A0(left/jl), g1=B0(right/jr), g2=O0(s2mv), g3=s1, g4=s2
// g_P[tok][160]: per-token scalar-head results, consumed by gb_kernel.
// ---------------------------------------------------------------------------
#define MAX_TOK 32768
__device__ float g_T[64 * 160];
__device__ float g_P[MAX_TOK * 160];

__global__ void init_transpose(const float* __restrict__ wLs, const float* __restrict__ wRs,
                               const float* __restrict__ wJLs, const float* __restrict__ wJRs,
                               const float* __restrict__ wS2mv, const float* __restrict__ wS2s)
{
    const int idx = blockIdx.x * blockDim.x + threadIdx.x;   // 0..10239
    if (idx >= 64 * 160) return;
    const int s = idx / 160;
    const int c = idx - s * 160;
    const int g = c >> 5;
    const int k = c & 31;
    float v;
    if (g == 0)      v = (k < 16) ? wLs[k * 64 + s] : wJLs[(k - 16) * 64 + s];
    else if (g == 1) v = (k < 16) ? wRs[k * 64 + s] : wJRs[(k - 16) * 64 + s];
    else if (g == 2) v = wS2mv[k * 64 + s];
    else if (g == 3) v = wS2s[k * 64 + s];
    else             v = wS2s[(32 + k) * 64 + s];
    g_T[idx] = v;
}

// Scalar-head matmul: [ntok,64] @ [64,160] -> g_P. 8 tokens (4 packed pairs)
// per warp iteration; weights from L1-resident g_T; f32x2 math.
__global__ void __launch_bounds__(256, 1)
scalar_head_kernel(const float* __restrict__ scal, int ntok)
{
    const int lane = threadIdx.x & 31;
    const int wid  = threadIdx.x >> 5;
    const int gw   = blockIdx.x * 8 + wid;
    const int nw   = gridDim.x * 8;
    const int noct = ntok >> 3;                   // ntok multiple of 8

    for (int o = gw; o < noct; o += nw) {
        const int t0 = o * 8;
        ull acc[5][4];
        #pragma unroll
        for (int g = 0; g < 5; ++g)
            #pragma unroll
            for (int u = 0; u < 4; ++u) acc[g][u] = 0ULL;

        for (int s4 = 0; s4 < 16; ++s4) {
            float4 sv[8];
            #pragma unroll
            for (int t = 0; t < 8; ++t)
                sv[t] = __ldg(reinterpret_cast<const float4*>(scal + (size_t)(t0 + t) * 64) + s4);
            #pragma unroll
            for (int k = 0; k < 4; ++k) {
                const int s = s4 * 4 + k;
                const float* ts = g_T + s * 160 + lane;
                const ull w0 = dup2(__ldg(ts));
                const ull w1 = dup2(__ldg(ts + 32));
                const ull w2 = dup2(__ldg(ts + 64));
                const ull w3 = dup2(__ldg(ts + 96));
                const ull w4 = dup2(__ldg(ts + 128));
                #pragma unroll
                for (int u = 0; u < 4; ++u) {
                    const float xa = (k == 0) ? sv[2*u].x : (k == 1) ? sv[2*u].y
                                   : (k == 2) ? sv[2*u].z : sv[2*u].w;
                    const float xb = (k == 0) ? sv[2*u+1].x : (k == 1) ? sv[2*u+1].y
                                   : (k == 2) ? sv[2*u+1].z : sv[2*u+1].w;
                    const ull x = pack2(xa, xb);
                    acc[0][u] = fma2(w0, x, acc[0][u]);
                    acc[1][u] = fma2(w1, x, acc[1][u]);
                    acc[2][u] = fma2(w2, x, acc[2][u]);
                    acc[3][u] = fma2(w3, x, acc[3][u]);
                    acc[4][u] = fma2(w4, x, acc[4][u]);
                }
            }
        }
        #pragma unroll
        for (int u = 0; u < 4; ++u) {
            float* pa = g_P + (size_t)(t0 + 2*u)     * 160 + lane;
            float* pb = g_P + (size_t)(t0 + 2*u + 1) * 160 + lane;
            #pragma unroll
            for (int g = 0; g < 5; ++g) {
                float a, b;
                unpack2(acc[g][u], a, b);
                pa[g * 32] = a;
                pb[g * 32] = b;
            }
        }
    }
}

// ---------------------------------------------------------------------------
// Main kernel: 12 warps, token pair per warp (identical to R11's 152 us
// kernel — scalar head hoisted out, row-local negation in gp/jn).
// ---------------------------------------------------------------------------
#define NW 12
#define NTHREADS (NW * 32)

#define OFF_WA    0        // [32 i][9 b][32 lane]
#define OFF_WB    9216
#define OFF_WO    18432    // [32 c][9 b][32 o]
#define OFF_WM1   27648    // [32 c][32 o]
#define OFF_WM2   28672
#define OFF_STG   29696
// Per-warp staging: 32 rows x 32 floats (XOR-swizzled ulonglong2 slots),
// reused for pair-interleaved x THEN hidden.
#define STG_PER_WARP 1024
#define SMEM_FLOATS (OFF_STG + NW * STG_PER_WARP)
#define SMEM_BYTES  (SMEM_FLOATS * 4)      // 167,936 B

__global__ void __launch_bounds__(NTHREADS, 1)
gb_kernel(const float* __restrict__ mv,      // [ntok][32][16]
          const float* __restrict__ refmv,   // [ntok][16]
          const float* __restrict__ wLmv,
          const float* __restrict__ wRmv,
          const float* __restrict__ wJLmv,
          const float* __restrict__ wJRmv,
          const float* __restrict__ wOmv,    // [32 o][32 c][9 b]
          const float* __restrict__ wMvs2s,  // [64 o][32 c]
          float* __restrict__ out,           // [ntok][32][16]
          float* __restrict__ outS,          // [ntok][64]
          int ntok)
{
    extern __shared__ float sm[];
    float* WA  = sm + OFF_WA;
    float* WB  = sm + OFF_WB;
    float* WO  = sm + OFF_WO;
    float* WM1 = sm + OFF_WM1;
    float* WM2 = sm + OFF_WM2;

    const int tid  = threadIdx.x;
    const int lane = tid & 31;
    const int wid  = tid >> 5;

    // ---- stage mv weights (lane-permuted) ----
    // lane<16: A=left[lane], B=right[lane];  lane>=16: A=jl[l-16], B=jr[l-16]
    for (int idx = tid; idx < 9216; idx += NTHREADS) {
        const int l   = idx & 31;
        const int off = idx >> 5;               // i*9+b
        WA[idx] = (l < 16) ? wLmv[l * 288 + off] : wJLmv[(l - 16) * 288 + off];
        WB[idx] = (l < 16) ? wRmv[l * 288 + off] : wJRmv[(l - 16) * 288 + off];
        WO[idx] = wOmv[l * 288 + off];
    }
    for (int idx = tid; idx < 1024; idx += NTHREADS) {
        const int l = idx & 31;
        const int c = idx >> 5;
        WM1[idx] = wMvs2s[l * 32 + c];
        WM2[idx] = wMvs2s[(32 + l) * 32 + c];
    }
    __syncthreads();

    float* buf = sm + OFF_STG + wid * STG_PER_WARP; // 32 rows x 32 floats (swizzled)

    const int gw = blockIdx.x * NW + wid;
    const int nw = gridDim.x * NW;
    const int npair = ntok >> 1;

    for (int p = gw; p < npair; p += nw) {
        const int tA = 2 * p, tB = 2 * p + 1;

        // ---- stage token-pair inputs ----
        // Row i: logical ulonglong2 slot t holds blades (2t, 2t+1) pairs;
        // physical slot = t ^ (i & 7).
        const float4* gxA = reinterpret_cast<const float4*>(mv + (size_t)tA * 512);
        const float4* gxB = reinterpret_cast<const float4*>(mv + (size_t)tB * 512);
        #pragma unroll
        for (int it = 0; it < 4; ++it) {
            const int c = it * 32 + lane;        // chunk 0..127
            const int i = c >> 2, q = c & 3;     // channel, quarter (blades 4q..4q+3)
            const float4 a = gxA[c];
            const float4 b = gxB[c];
            const int m  = i & 7;
            const int p0 = (2 * q) ^ m;          // slot for blades 4q,4q+1
            const int p1 = p0 ^ 1;               // slot for blades 4q+2,4q+3
            float* base = buf + i * 32;
            *reinterpret_cast<float4*>(base + p0 * 4) = make_float4(a.x, b.x, a.y, b.y);
            *reinterpret_cast<float4*>(base + p1 * 4) = make_float4(a.z, b.z, a.w, b.w);
        }
        const ull refp = pack2(refmv[(size_t)tA * 16 + 15], refmv[(size_t)tB * 16 + 15]);
        const float* Pa = g_P + (size_t)tA * 160;
        const float* Pb = g_P + (size_t)tB * 160;
        __syncwarp();

        // ---- input equi-linears owned by this lane (packed pair) ----
        ull A[16], Bv[16];
        A[0]  = pack2(__ldg(Pa + lane),      __ldg(Pb + lane));
        Bv[0] = pack2(__ldg(Pa + 32 + lane), __ldg(Pb + 32 + lane));
        #pragma unroll
        for (int j = 1; j < 16; ++j) { A[j] = 0ULL; Bv[j] = 0ULL; }

        for (int i0 = 0; i0 < 32; i0 += 8) {
            #pragma unroll
            for (int k = 0; k < 8; ++k) {
                const int i = i0 + k;
                ull xr[16];
                const float* base = buf + i * 32;
                #pragma unroll
                for (int t = 0; t < 8; ++t) {    // broadcast reads, swizzled slots
                    const ulonglong2 v =
                        *reinterpret_cast<const ulonglong2*>(base + ((t ^ k) * 4));
                    xr[2*t] = v.x; xr[2*t+1] = v.y;
                }
                ull wa[9], wb[9];
                #pragma unroll
                for (int b = 0; b < 9; ++b) {
                    wa[b] = dup2(WA[(i * 9 + b) * 32 + lane]);
                    wb[b] = dup2(WB[(i * 9 + b) * 32 + lane]);
                }
                ga::linAcc2(A, wa, xr);
                ga::linAcc2(Bv, wb, xr);
            }
        }
        __syncwarp();   // all lanes done reading x staging

        // ---- bilinear: gp on lanes 0..15, join on lanes 16..31 ----
        ull h[16];
        #pragma unroll
        for (int j = 0; j < 16; ++j) h[j] = 0ULL;
        if (lane < 16) {
            ga::gpAll(A, Bv, h, typename ga::mkseq<16>::type{});
        } else {
            ga::jnAll(A, Bv, h, typename ga::mkseq<16>::type{});
            #pragma unroll
            for (int j = 0; j < 16; ++j) h[j] = mul2(h[j], refp);
        }
        // stage hidden (lane = channel) into the SAME buffer, swizzled
        {
            float* base = buf + lane * 32;
            const int m = lane & 7;
            #pragma unroll
            for (int t = 0; t < 8; ++t)
                *reinterpret_cast<ulonglong2*>(base + ((t ^ m) * 4)) =
                    make_ulonglong2(h[2*t], h[2*t+1]);
        }
        __syncwarp();

        // ---- output equi-linear + scalar heads: lane = output channel o ----
        ull O[16];
        O[0] = pack2(__ldg(Pa + 64 + lane), __ldg(Pb + 64 + lane));
        #pragma unroll
        for (int j = 1; j < 16; ++j) O[j] = 0ULL;
        ull os1 = pack2(__ldg(Pa + 96 + lane),  __ldg(Pb + 96 + lane));
        ull os2 = pack2(__ldg(Pa + 128 + lane), __ldg(Pb + 128 + lane));

        for (int c0 = 0; c0 < 32; c0 += 8) {
            #pragma unroll
            for (int k = 0; k < 8; ++k) {
                const int c = c0 + k;
                ull hr[16];
                const float* base = buf + c * 32;
                #pragma unroll
                for (int t = 0; t < 8; ++t) {    // broadcast reads, swizzled slots
                    const ulonglong2 v =
                        *reinterpret_cast<const ulonglong2*>(base + ((t ^ k) * 4));
                    hr[2*t] = v.x; hr[2*t+1] = v.y;
                }
                ull wo[9];
                #pragma unroll
                for (int b = 0; b < 9; ++b) wo[b] = dup2(WO[(c * 9 + b) * 32 + lane]);
                ga::linAcc2(O, wo, hr);

                os1 = fma2(dup2(WM1[c * 32 + lane]), hr[0], os1);
                os2 = fma2(dup2(WM2[c * 32 + lane]), hr[0], os2);
            }
        }

        // ---- write outputs ----
        {
            float Oa[16], Ob[16];
            #pragma unroll
            for (int j = 0; j < 16; ++j) unpack2(O[j], Oa[j], Ob[j]);
            float* omA = out + (size_t)tA * 512 + lane * 16;
            float* omB = out + (size_t)tB * 512 + lane * 16;
            #pragma unroll
            for (int m = 0; m < 4; ++m) {
                *reinterpret_cast<float4*>(omA + m * 4) =
                    make_float4(Oa[m*4+0], Oa[m*4+1], Oa[m*4+2], Oa[m*4+3]);
                *reinterpret_cast<float4*>(omB + m * 4) =
                    make_float4(Ob[m*4+0], Ob[m*4+1], Ob[m*4+2], Ob[m*4+3]);
            }
        }
        {
            float a1, b1, a2, b2;
            unpack2(os1, a1, b1);
            unpack2(os2, a2, b2);
            outS[(size_t)tA * 64 + lane]      = a1;
            outS[(size_t)tA * 64 + 32 + lane] = a2;
            outS[(size_t)tB * 64 + lane]      = b1;
            outS[(size_t)tB * 64 + 32 + lane] = b2;
        }
        __syncwarp();   // staging reused next iteration
    }
}

// ---------------------------------------------------------------------------
// Launch
// ---------------------------------------------------------------------------
extern "C" void kernel_launch(void* const* d_in, const int* in_sizes, int n_in,
                              void* d_out, int out_size) {
    const float* mv     = (const float*)d_in[0];
    const float* refmv  = (const float*)d_in[1];
    const float* scal   = (const float*)d_in[2];
    // d_in[3..5] = basis, gp, jn (structure hardcoded at compile time)
    const float* wLmv   = (const float*)d_in[6];
    const float* wLs    = (const float*)d_in[7];
    const float* wRmv   = (const float*)d_in[8];
    const float* wRs    = (const float*)d_in[9];
    const float* wJLmv  = (const float*)d_in[10];
    const float* wJLs   = (const float*)d_in[11];
    const float* wJRmv  = (const float*)d_in[12];
    const float* wJRs   = (const float*)d_in[13];
    const float* wOmv   = (const float*)d_in[14];
    const float* wS2mv  = (const float*)d_in[15];
    const float* wMvs2s = (const float*)d_in[16];
    const float* wS2s   = (const float*)d_in[17];

    const int ntok = in_sizes[0] / 512;          // 32768
    float* out  = (float*)d_out;                 // [ntok*512] out_mv
    float* outS = out + (size_t)ntok * 512;      // [ntok*64]  out_s

    int dev = 0;
    cudaGetDevice(&dev);
    int nsm = 148;
    cudaDeviceGetAttribute(&nsm, cudaDevAttrMultiProcessorCount, dev);

    // Stage 0: one-shot transposed scalar-head weight table (the scattered
    // gather happens exactly once, not per-block).
    init_transpose<<<40, 256>>>(wLs, wRs, wJLs, wJRs, wS2mv, wS2s);

    // Stage 1: scalar-head matmul -> g_P (f32x2, L1-resident weights)
    scalar_head_kernel<<<2 * nsm, 256>>>(scal, ntok);

    // Stage 2: main geometric-bilinear kernel (unchanged from the 152 us run)
    cudaFuncSetAttribute(gb_kernel, cudaFuncAttributeMaxDynamicSharedMemorySize, SMEM_BYTES);
    gb_kernel<<<nsm, NTHREADS, SMEM_BYTES>>>(
        mv, refmv,
        wLmv, wRmv, wJLmv, wJRmv, wOmv, wMvs2s,
        out, outS, ntok);
}